// round 15
// baseline (speedup 1.0000x reference)
#include <cuda_runtime.h>
#include <cuda_bf16.h>

typedef unsigned long long ULL;

// ---------------- f32x2 packed helpers (sm_100+) ----------------
__device__ __forceinline__ ULL ffma2(ULL a, ULL b, ULL c) {
    ULL d;
    asm("fma.rn.f32x2 %0, %1, %2, %3;" : "=l"(d) : "l"(a), "l"(b), "l"(c));
    return d;
}
__device__ __forceinline__ ULL fadd2(ULL a, ULL b) {
    ULL d;
    asm("add.rn.f32x2 %0, %1, %2;" : "=l"(d) : "l"(a), "l"(b));
    return d;
}
__device__ __forceinline__ ULL dup2(float w) {
    unsigned u = __float_as_uint(w);
    ULL d;
    asm("mov.b64 %0, {%1, %1};" : "=l"(d) : "r"(u));
    return d;
}
__device__ __forceinline__ ULL pack2(float lo, float hi) {
    ULL d;
    unsigned a = __float_as_uint(lo), b = __float_as_uint(hi);
    asm("mov.b64 %0, {%1, %2};" : "=l"(d) : "r"(a), "r"(b));
    return d;
}
__device__ __forceinline__ void unpack2(ULL v, float& lo, float& hi) {
    unsigned a, b;
    asm("mov.b64 {%0, %1}, %2;" : "=r"(a), "=r"(b) : "l"(v));
    lo = __uint_as_float(a);
    hi = __uint_as_float(b);
}

// Single-op MUFU tanh (sm_75+). Measured final rel_err 3.6e-6.
__device__ __forceinline__ float tanh_fast(float x) {
    float r;
    asm("tanh.approx.f32 %0, %1;" : "=f"(r) : "f"(x));
    return r;
}

// ---------------- config ----------------
// B=4096, T=2048, F=8, H=32, O=8
// R13: exactly ONE warp per SMSP. Lineage data: a lone 4-row warp steps in
// ~260 cyc while 2-warp SMSPs lock phases and step in ~490 (the wall in
// R5/R8/R10/R11). So: 512 warps x 8 rows, launched as 128 blocks x 128
// threads -> each SM gets 4 warps = one per SMSP (wid%4), no co-resident
// pair, no phase locking. Latency hiding is intra-warp: the 8 rows form
// two GROUPS (G0 = pairs 0/1, G1 = pairs 2/3); G0's tail overlaps G1's
// FMA block in program order. R7 tried this shape and failed (800
// cyc/step); R13 removes R7's defects: xp software-pipelined off the
// critical path (R8), no per-step __syncwarp (R10), tail reorder (R10).
// Floor: 160 FFMA2 x rt2 = 320 cyc/step.
// Per-warp layout (per group): lanes 0-15 own pairA, lanes 16-31 pairB;
// each lane computes h rows llo and llo+16 (W_hh rows dup'd in regs,
// SHARED by both groups).
#define TT    2048
#define FF    8
#define HH    32
#define OO    8
#define CHUNK 8       // timesteps of x staged per SMEM refill
#define NW    4       // warps per block (one per SMSP)
#define NP    4       // pairs per warp (8 rows)
#define HPAD  34      // ULL stride between pair h buffers (+4 banks; 16B mult)
#define XPAD  66      // ULL stride between pair x buffers (+4 banks; 16B mult)

__global__ void __launch_bounds__(32 * NW, 1)
rnn_fused_kernel(const float* __restrict__ x,
                 const float* __restrict__ W_ih,
                 const float* __restrict__ W_hh,
                 const float* __restrict__ b_ih,
                 const float* __restrict__ b_hh,
                 const float* __restrict__ W_out,
                 const float* __restrict__ b_out,
                 float* __restrict__ out)
{
    // Per-warp double-buffered h and x staging (warp-private slices; no
    // cross-warp traffic, no __syncthreads anywhere in the loop).
    __shared__ __align__(16) ULL hb[NW][2][NP][HPAD];
    __shared__ __align__(16) ULL xb[NW][2][NP][XPAD];

    const int tid  = threadIdx.x;
    const int wip  = tid >> 5;          // 0..3 == SMSP id
    const int lane = tid & 31;
    const int llo  = lane & 15;
    const int half = lane >> 4;
    const size_t base = (size_t)blockIdx.x * (2 * NP * NW)
                      + (size_t)wip * (2 * NP);   // first of 8 rows

    // ---- weights: W_hh rows llo and llo+16, duplicated for f32x2 ----
    ULL wA[HH], wB[HH];
    {
        const float4* ra = (const float4*)(W_hh + llo * HH);
        const float4* rb = (const float4*)(W_hh + (llo + 16) * HH);
        #pragma unroll
        for (int k = 0; k < HH / 4; ++k) {
            float4 va = ra[k], vb = rb[k];
            wA[4*k+0] = dup2(va.x); wA[4*k+1] = dup2(va.y);
            wA[4*k+2] = dup2(va.z); wA[4*k+3] = dup2(va.w);
            wB[4*k+0] = dup2(vb.x); wB[4*k+1] = dup2(vb.y);
            wB[4*k+2] = dup2(vb.z); wB[4*k+3] = dup2(vb.w);
        }
    }
    ULL wihA[FF], wihB[FF];
    {
        const float4* ra = (const float4*)(W_ih + llo * FF);
        const float4* rb = (const float4*)(W_ih + (llo + 16) * FF);
        #pragma unroll
        for (int k = 0; k < FF / 4; ++k) {
            float4 va = ra[k], vb = rb[k];
            wihA[4*k+0] = dup2(va.x); wihA[4*k+1] = dup2(va.y);
            wihA[4*k+2] = dup2(va.z); wihA[4*k+3] = dup2(va.w);
            wihB[4*k+0] = dup2(vb.x); wihB[4*k+1] = dup2(vb.y);
            wihB[4*k+2] = dup2(vb.z); wihB[4*k+3] = dup2(vb.w);
        }
    }
    const ULL biasA = dup2(b_ih[llo]      + b_hh[llo]);
    const ULL biasB = dup2(b_ih[llo + 16] + b_hh[llo + 16]);

    // h0 = 0 for all 4 pairs
    hb[wip][0][half][llo]          = 0ULL;
    hb[wip][0][half][llo + 16]     = 0ULL;
    hb[wip][0][2 + half][llo]      = 0ULL;
    hb[wip][0][2 + half][llo + 16] = 0ULL;

    const int NCHUNK = TT / CHUNK;   // 256

    // ---- x prefetch/staging: 8 rows x 16 float4 per chunk, 4 per lane ----
    float4 pre[4];
    #pragma unroll
    for (int k = 0; k < 4; ++k) {
        const int i = lane + 32 * k;
        pre[k] = *(const float4*)(x + (base + (i >> 4)) * (size_t)(TT * FF)
                                    + (i & 15) * 4);
    }
    // stage chunk 0 into buffer 0 (interleaved (rowEven,rowOdd) per pair)
    {
        #pragma unroll
        for (int k = 0; k < 4; ++k) {
            const int i    = lane + 32 * k;
            const int row  = i >> 4;
            const int pos  = i & 15;
            const int pair = row >> 1;
            const int slot = row & 1;
            float* xs = (float*)&xb[wip][0][pair][0];
            const float4 v = pre[k];
            xs[(pos*4 + 0) * 2 + slot] = v.x;
            xs[(pos*4 + 1) * 2 + slot] = v.y;
            xs[(pos*4 + 2) * 2 + slot] = v.z;
            xs[(pos*4 + 3) * 2 + slot] = v.w;
        }
    }
    __syncwarp();

    // initial xp for t=0, both groups (bias included)
    ULL xpA0, xpB0, xpA1, xpB1;
    #pragma unroll
    for (int g = 0; g < 2; ++g) {
        const ULL* xr = &xb[wip][0][2 * g + half][0];
        ULL p0 = biasA, p1 = 0ULL, q0 = biasB, q1 = 0ULL;
        #pragma unroll
        for (int f = 0; f < FF; f += 2) {
            ulonglong2 xv = *(const ulonglong2*)&xr[f];
            p0 = ffma2(xv.x, wihA[f],     p0);
            p1 = ffma2(xv.y, wihA[f + 1], p1);
            q0 = ffma2(xv.x, wihB[f],     q0);
            q1 = ffma2(xv.y, wihB[f + 1], q1);
        }
        if (g == 0) { xpA0 = fadd2(p0, p1); xpB0 = fadd2(q0, q1); }
        else        { xpA1 = fadd2(p0, p1); xpB1 = fadd2(q0, q1); }
    }

    // prefetch chunk 1
    #pragma unroll
    for (int k = 0; k < 4; ++k) {
        const int i = lane + 32 * k;
        pre[k] = *(const float4*)(x + (base + (i >> 4)) * (size_t)(TT * FF)
                                    + (size_t)(CHUNK * FF) + (i & 15) * 4);
    }

    for (int c = 0; c < NCHUNK; ++c) {
        // stage chunk c+1 into buffer (c+1)&1 (needed by step s=7's xp-next)
        if (c + 1 < NCHUNK) {
            const int buf = (c + 1) & 1;
            #pragma unroll
            for (int k = 0; k < 4; ++k) {
                const int i    = lane + 32 * k;
                const int row  = i >> 4;
                const int pos  = i & 15;
                const int pair = row >> 1;
                const int slot = row & 1;
                float* xs = (float*)&xb[wip][buf][pair][0];
                const float4 v = pre[k];
                xs[(pos*4 + 0) * 2 + slot] = v.x;
                xs[(pos*4 + 1) * 2 + slot] = v.y;
                xs[(pos*4 + 2) * 2 + slot] = v.z;
                xs[(pos*4 + 3) * 2 + slot] = v.w;
            }
        }
        if (c + 2 < NCHUNK) {
            #pragma unroll
            for (int k = 0; k < 4; ++k) {
                const int i = lane + 32 * k;
                pre[k] = *(const float4*)(x + (base + (i >> 4)) * (size_t)(TT * FF)
                                            + (size_t)(c + 2) * (CHUNK * FF)
                                            + (i & 15) * 4);
            }
        }
        // guards cross-half-warp x staging (once per CHUNK steps)
        __syncwarp();

        #pragma unroll
        for (int s = 0; s < CHUNK; ++s) {
            const int t = c * CHUNK + s;
            const ULL* hr0 = &hb[wip][t & 1][half][0];
            const ULL* hr1 = &hb[wip][t & 1][2 + half][0];

            // ---- G0 recurrent matvec (from pipelined xp) ----
            ULL a0 = xpA0, a1 = 0ULL, c0 = xpB0, c1 = 0ULL;
            #pragma unroll
            for (int j = 0; j < HH; j += 2) {
                ulonglong2 hv = *(const ulonglong2*)&hr0[j];
                a0 = ffma2(hv.x, wA[j],     a0);
                a1 = ffma2(hv.y, wA[j + 1], a1);
                c0 = ffma2(hv.x, wB[j],     c0);
                c1 = ffma2(hv.y, wB[j + 1], c1);
            }
            // ---- G1 recurrent matvec (independent; covers G0's chain) ----
            ULL d0 = xpA1, d1 = 0ULL, e0 = xpB1, e1 = 0ULL;
            #pragma unroll
            for (int j = 0; j < HH; j += 2) {
                ulonglong2 hv = *(const ulonglong2*)&hr1[j];
                d0 = ffma2(hv.x, wA[j],     d0);
                d1 = ffma2(hv.y, wA[j + 1], d1);
                e0 = ffma2(hv.x, wB[j],     e0);
                e1 = ffma2(hv.y, wB[j + 1], e1);
            }

            const ULL* xn0 = (s < CHUNK - 1) ? &xb[wip][c & 1][half][(s + 1) * FF]
                                             : &xb[wip][(c + 1) & 1][half][0];
            const ULL* xn1 = (s < CHUNK - 1) ? &xb[wip][c & 1][2 + half][(s + 1) * FF]
                                             : &xb[wip][(c + 1) & 1][2 + half][0];
            ULL* hw = &hb[wip][(t + 1) & 1][0][0];

            // ---- G0 tail: fadd -> tanh issue -> xp-next (fills tanh
            // latency) -> STS. Overlaps G1's FMA block above. ----
            {
                const ULL accA = fadd2(a0, a1);
                const ULL accB = fadd2(c0, c1);
                float u0, u1, u2, u3;
                unpack2(accA, u0, u1);
                unpack2(accB, u2, u3);
                const float r0 = tanh_fast(u0);
                const float r1 = tanh_fast(u1);
                const float r2 = tanh_fast(u2);
                const float r3 = tanh_fast(u3);

                ULL p0 = biasA, p1 = 0ULL, q0 = biasB, q1 = 0ULL;
                #pragma unroll
                for (int f = 0; f < FF; f += 2) {
                    ulonglong2 xv = *(const ulonglong2*)&xn0[f];
                    p0 = ffma2(xv.x, wihA[f],     p0);
                    p1 = ffma2(xv.y, wihA[f + 1], p1);
                    q0 = ffma2(xv.x, wihB[f],     q0);
                    q1 = ffma2(xv.y, wihB[f + 1], q1);
                }
                xpA0 = fadd2(p0, p1);
                xpB0 = fadd2(q0, q1);

                ULL* h0 = hw + half * HPAD;
                h0[llo]      = pack2(r0, r1);
                h0[llo + 16] = pack2(r2, r3);
            }
            // ---- G1 tail ----
            {
                const ULL accA = fadd2(d0, d1);
                const ULL accB = fadd2(e0, e1);
                float u0, u1, u2, u3;
                unpack2(accA, u0, u1);
                unpack2(accB, u2, u3);
                const float r0 = tanh_fast(u0);
                const float r1 = tanh_fast(u1);
                const float r2 = tanh_fast(u2);
                const float r3 = tanh_fast(u3);

                ULL p0 = biasA, p1 = 0ULL, q0 = biasB, q1 = 0ULL;
                #pragma unroll
                for (int f = 0; f < FF; f += 2) {
                    ulonglong2 xv = *(const ulonglong2*)&xn1[f];
                    p0 = ffma2(xv.x, wihA[f],     p0);
                    p1 = ffma2(xv.y, wihA[f + 1], p1);
                    q0 = ffma2(xv.x, wihB[f],     q0);
                    q1 = ffma2(xv.y, wihB[f + 1], q1);
                }
                xpA1 = fadd2(p0, p1);
                xpB1 = fadd2(q0, q1);

                ULL* h1 = hw + (2 + half) * HPAD;
                h1[llo]      = pack2(r0, r1);
                h1[llo + 16] = pack2(r2, r3);
            }
            // NO per-step __syncwarp: all h exchange is intra-half-warp,
            // same-warp smem ops are in-order (R10-proven).
        }
    }

    __syncwarp();

    // ---- output head: y = h_final @ W_out^T + b_out ----
    // T=2048 even -> final h in buffer 0.
    if (llo < OO) {
        #pragma unroll
        for (int g = 0; g < 2; ++g) {
            const ULL* hf = &hb[wip][0][2 * g + half][0];
            float ya = b_out[llo];
            float yb = ya;
            #pragma unroll
            for (int j = 0; j < HH; ++j) {
                float ha, hc;
                unpack2(hf[j], ha, hc);
                const float wv = W_out[llo * HH + j];
                ya = fmaf(wv, ha, ya);
                yb = fmaf(wv, hc, yb);
            }
            const size_t r0 = base + 2 * (2 * g + half);
            out[r0 * OO + llo]       = ya;
            out[(r0 + 1) * OO + llo] = yb;
        }
    }
}

extern "C" void kernel_launch(void* const* d_in, const int* in_sizes, int n_in,
                              void* d_out, int out_size)
{
    const float* x     = (const float*)d_in[0];
    const float* W_ih  = (const float*)d_in[1];
    const float* W_hh  = (const float*)d_in[2];
    const float* b_ih  = (const float*)d_in[3];
    const float* b_hh  = (const float*)d_in[4];
    const float* W_out = (const float*)d_in[5];
    const float* b_out = (const float*)d_in[6];
    float* out = (float*)d_out;

    // 4096 rows / (4 warps x 8 rows) = 128 blocks of 128 threads;
    // 1 block/SM, exactly one warp per SMSP (wid%4).
    rnn_fused_kernel<<<128, 32 * NW>>>(x, W_ih, W_hh, b_ih, b_hh,
                                       W_out, b_out, out);
}

// round 16
// speedup vs baseline: 1.0221x; 1.0221x over previous
#include <cuda_runtime.h>
#include <cuda_bf16.h>

typedef unsigned long long ULL;

// ---------------- f32x2 packed helpers (sm_100+) ----------------
__device__ __forceinline__ ULL ffma2(ULL a, ULL b, ULL c) {
    ULL d;
    asm("fma.rn.f32x2 %0, %1, %2, %3;" : "=l"(d) : "l"(a), "l"(b), "l"(c));
    return d;
}
__device__ __forceinline__ ULL fadd2(ULL a, ULL b) {
    ULL d;
    asm("add.rn.f32x2 %0, %1, %2;" : "=l"(d) : "l"(a), "l"(b));
    return d;
}
__device__ __forceinline__ ULL dup2(float w) {
    unsigned u = __float_as_uint(w);
    ULL d;
    asm("mov.b64 %0, {%1, %1};" : "=l"(d) : "r"(u));
    return d;
}
__device__ __forceinline__ ULL pack2(float lo, float hi) {
    ULL d;
    unsigned a = __float_as_uint(lo), b = __float_as_uint(hi);
    asm("mov.b64 %0, {%1, %2};" : "=l"(d) : "r"(a), "r"(b));
    return d;
}
__device__ __forceinline__ void unpack2(ULL v, float& lo, float& hi) {
    unsigned a, b;
    asm("mov.b64 {%0, %1}, %2;" : "=r"(a), "=r"(b) : "l"(v));
    lo = __uint_as_float(a);
    hi = __uint_as_float(b);
}

// Single-op MUFU tanh (sm_75+). Measured final rel_err 3.6e-6.
__device__ __forceinline__ float tanh_fast(float x) {
    float r;
    asm("tanh.approx.f32 %0, %1;" : "=f"(r) : "f"(x));
    return r;
}

// ---------------- config ----------------
// B=4096, T=2048, F=8, H=32, O=8
// Base = R11 (best, 559us): 128 blocks x 256 threads, 1 block/SM; warps w
// and w+4 share an SMSP; warps 4-7 get a ~190-cyc start skew. 4 rows/warp
// (2 f32x2 pairs, half-warp split, W_hh rows llo/llo+16 dup'd in regs).
// R16 adds a CROSS-STEP LDS PIPELINE: after each step's h-STS, preload the
// first 4 h pairs (2x LDS.128 -> regs) for the NEXT step, then run the
// xp-next FMA block (32 issue cyc) which hides the 29-cyc LDS latency.
// Next step's FMA block starts from registers; the remaining 14 LDS issue
// inside the FMA block where latency is already covered. Removes the
// phase-lock-double-counted first-load stall (~58 cyc of the 491-cyc wall).
#define TT    2048
#define FF    8
#define HH    32
#define OO    8
#define CHUNK 8       // timesteps of x staged per SMEM refill
#define NW    8       // warps per block
#define HPAD  34      // ULL stride between pair h buffers (+4 banks; 16B mult)
#define XPAD  66      // ULL stride between pair x buffers (+4 banks; 16B mult)

__global__ void __launch_bounds__(32 * NW, 1)
rnn_fused_kernel(const float* __restrict__ x,
                 const float* __restrict__ W_ih,
                 const float* __restrict__ W_hh,
                 const float* __restrict__ b_ih,
                 const float* __restrict__ b_hh,
                 const float* __restrict__ W_out,
                 const float* __restrict__ b_out,
                 float* __restrict__ out)
{
    // Per-warp double-buffered h and x staging (warp-private slices).
    __shared__ __align__(16) ULL hb[NW][2][2][HPAD];
    __shared__ __align__(16) ULL xb[NW][2][2][XPAD];

    const int tid  = threadIdx.x;
    const int wip  = tid >> 5;          // 0..7
    const int lane = tid & 31;
    const int llo  = lane & 15;
    const int half = lane >> 4;
    const size_t base = (size_t)blockIdx.x * (4 * NW) + (size_t)wip * 4;

    // ---- ANTIPHASE SKEW: warps 4-7 (wid%4 partners of 0-3) burn ~190
    // cycles in a dependent FMA chain before starting (R11-proven). ----
    if (wip >= 4) {
        float z = 1.0f;
        #pragma unroll
        for (int i = 0; i < 48; ++i)
            asm volatile("fma.rn.f32 %0, %0, %1, %2;"
                         : "+f"(z) : "f"(1.0f), "f"(0.0f));
    }

    // ---- weights: W_hh rows llo and llo+16, duplicated for f32x2 ----
    ULL wA[HH], wB[HH];
    {
        const float4* ra = (const float4*)(W_hh + llo * HH);
        const float4* rb = (const float4*)(W_hh + (llo + 16) * HH);
        #pragma unroll
        for (int k = 0; k < HH / 4; ++k) {
            float4 va = ra[k], vb = rb[k];
            wA[4*k+0] = dup2(va.x); wA[4*k+1] = dup2(va.y);
            wA[4*k+2] = dup2(va.z); wA[4*k+3] = dup2(va.w);
            wB[4*k+0] = dup2(vb.x); wB[4*k+1] = dup2(vb.y);
            wB[4*k+2] = dup2(vb.z); wB[4*k+3] = dup2(vb.w);
        }
    }
    ULL wihA[FF], wihB[FF];
    {
        const float4* ra = (const float4*)(W_ih + llo * FF);
        const float4* rb = (const float4*)(W_ih + (llo + 16) * FF);
        #pragma unroll
        for (int k = 0; k < FF / 4; ++k) {
            float4 va = ra[k], vb = rb[k];
            wihA[4*k+0] = dup2(va.x); wihA[4*k+1] = dup2(va.y);
            wihA[4*k+2] = dup2(va.z); wihA[4*k+3] = dup2(va.w);
            wihB[4*k+0] = dup2(vb.x); wihB[4*k+1] = dup2(vb.y);
            wihB[4*k+2] = dup2(vb.z); wihB[4*k+3] = dup2(vb.w);
        }
    }
    const ULL biasA = dup2(b_ih[llo]      + b_hh[llo]);
    const ULL biasB = dup2(b_ih[llo + 16] + b_hh[llo + 16]);

    // h0 = 0 for both pairs
    hb[wip][0][half][llo]      = 0ULL;
    hb[wip][0][half][llo + 16] = 0ULL;

    const int NCHUNK = TT / CHUNK;   // 256

    // ---- x prefetch/staging: 4 rows x 16 float4 per chunk, 2 per lane ----
    float4 pre0, pre1;
    {   // load chunk 0
        const int i0 = lane, i1 = lane + 32;
        pre0 = *(const float4*)(x + (base + (i0 >> 4)) * (size_t)(TT * FF) + (i0 & 15) * 4);
        pre1 = *(const float4*)(x + (base + (i1 >> 4)) * (size_t)(TT * FF) + (i1 & 15) * 4);
    }
    // stage chunk 0 into buffer 0 (interleaved (rowEven,rowOdd) per pair)
    {
        #pragma unroll
        for (int k = 0; k < 2; ++k) {
            const int i    = lane + 32 * k;
            const int row  = i >> 4;
            const int pos  = i & 15;
            const int pair = row >> 1;
            const int slot = row & 1;
            float* xs = (float*)&xb[wip][0][pair][0];
            const float4 v = (k == 0) ? pre0 : pre1;
            xs[(pos*4 + 0) * 2 + slot] = v.x;
            xs[(pos*4 + 1) * 2 + slot] = v.y;
            xs[(pos*4 + 2) * 2 + slot] = v.z;
            xs[(pos*4 + 3) * 2 + slot] = v.w;
        }
    }
    __syncwarp();

    // initial xp for t=0 (bias included)
    ULL xpA, xpB;
    {
        const ULL* xr = &xb[wip][0][half][0];
        ULL p0 = biasA, p1 = 0ULL, q0 = biasB, q1 = 0ULL;
        #pragma unroll
        for (int f = 0; f < FF; f += 2) {
            ulonglong2 xv = *(const ulonglong2*)&xr[f];
            p0 = ffma2(xv.x, wihA[f],     p0);
            p1 = ffma2(xv.y, wihA[f + 1], p1);
            q0 = ffma2(xv.x, wihB[f],     q0);
            q1 = ffma2(xv.y, wihB[f + 1], q1);
        }
        xpA = fadd2(p0, p1);
        xpB = fadd2(q0, q1);
    }

    // cross-step pipeline registers: h pairs j=0..3 for the NEXT step.
    // h0 = 0, so the t=0 preload is just zeros.
    ulonglong2 h01, h23;
    h01.x = 0ULL; h01.y = 0ULL;
    h23.x = 0ULL; h23.y = 0ULL;

    // prefetch chunk 1
    {
        const int i0 = lane, i1 = lane + 32;
        pre0 = *(const float4*)(x + (base + (i0 >> 4)) * (size_t)(TT * FF)
                                  + (size_t)(CHUNK * FF) + (i0 & 15) * 4);
        pre1 = *(const float4*)(x + (base + (i1 >> 4)) * (size_t)(TT * FF)
                                  + (size_t)(CHUNK * FF) + (i1 & 15) * 4);
    }

    for (int c = 0; c < NCHUNK; ++c) {
        // stage chunk c+1 into buffer (c+1)&1 (needed by step s=7's xp-next)
        if (c + 1 < NCHUNK) {
            const int buf = (c + 1) & 1;
            #pragma unroll
            for (int k = 0; k < 2; ++k) {
                const int i    = lane + 32 * k;
                const int row  = i >> 4;
                const int pos  = i & 15;
                const int pair = row >> 1;
                const int slot = row & 1;
                float* xs = (float*)&xb[wip][buf][pair][0];
                const float4 v = (k == 0) ? pre0 : pre1;
                xs[(pos*4 + 0) * 2 + slot] = v.x;
                xs[(pos*4 + 1) * 2 + slot] = v.y;
                xs[(pos*4 + 2) * 2 + slot] = v.z;
                xs[(pos*4 + 3) * 2 + slot] = v.w;
            }
        }
        if (c + 2 < NCHUNK) {
            const int i0 = lane, i1 = lane + 32;
            pre0 = *(const float4*)(x + (base + (i0 >> 4)) * (size_t)(TT * FF)
                                      + (size_t)(c + 2) * (CHUNK * FF) + (i0 & 15) * 4);
            pre1 = *(const float4*)(x + (base + (i1 >> 4)) * (size_t)(TT * FF)
                                      + (size_t)(c + 2) * (CHUNK * FF) + (i1 & 15) * 4);
        }
        // guards cross-half-warp x staging (once per CHUNK steps);
        // h01/h23 live in regs across this barrier (values preserved).
        __syncwarp();

        #pragma unroll
        for (int s = 0; s < CHUNK; ++s) {
            const int t = c * CHUNK + s;
            const ULL* hr = &hb[wip][t & 1][half][0];

            // ---- recurrent matvec: j=0..3 from PRELOADED regs, rest LDS ----
            ULL a0 = ffma2(h01.x, wA[0], xpA);
            ULL a1 = ffma2(h01.y, wA[1], 0ULL);
            ULL c0 = ffma2(h01.x, wB[0], xpB);
            ULL c1 = ffma2(h01.y, wB[1], 0ULL);
            a0 = ffma2(h23.x, wA[2], a0);
            a1 = ffma2(h23.y, wA[3], a1);
            c0 = ffma2(h23.x, wB[2], c0);
            c1 = ffma2(h23.y, wB[3], c1);
            #pragma unroll
            for (int j = 4; j < HH; j += 2) {
                ulonglong2 hv = *(const ulonglong2*)&hr[j];
                a0 = ffma2(hv.x, wA[j],     a0);
                a1 = ffma2(hv.y, wA[j + 1], a1);
                c0 = ffma2(hv.x, wB[j],     c0);
                c1 = ffma2(hv.y, wB[j + 1], c1);
            }
            const ULL accA = fadd2(a0, a1);
            const ULL accB = fadd2(c0, c1);

            // tanh (MUFU) ...
            float u0, u1, u2, u3;
            unpack2(accA, u0, u1);
            unpack2(accB, u2, u3);
            const float r0 = tanh_fast(u0);
            const float r1 = tanh_fast(u1);
            const float r2 = tanh_fast(u2);
            const float r3 = tanh_fast(u3);

            // h writeback (intra-half-warp; same-warp smem in-order)
            ULL* hw = &hb[wip][(t + 1) & 1][half][0];
            hw[llo]      = pack2(r0, r1);
            hw[llo + 16] = pack2(r2, r3);

            // ---- cross-step preload: first 4 h pairs of NEXT step; the
            // xp block below (32 issue cyc) hides the 29-cyc LDS latency.
            h01 = *(const ulonglong2*)&hw[0];
            h23 = *(const ulonglong2*)&hw[2];

            // ---- xp for t+1 (h-independent) ----
            {
                const ULL* xn = (s < CHUNK - 1)
                    ? &xb[wip][c & 1][half][(s + 1) * FF]
                    : &xb[wip][(c + 1) & 1][half][0];
                ULL p0 = biasA, p1 = 0ULL, q0 = biasB, q1 = 0ULL;
                #pragma unroll
                for (int f = 0; f < FF; f += 2) {
                    ulonglong2 xv = *(const ulonglong2*)&xn[f];
                    p0 = ffma2(xv.x, wihA[f],     p0);
                    p1 = ffma2(xv.y, wihA[f + 1], p1);
                    q0 = ffma2(xv.x, wihB[f],     q0);
                    q1 = ffma2(xv.y, wihB[f + 1], q1);
                }
                xpA = fadd2(p0, p1);
                xpB = fadd2(q0, q1);
            }
        }
    }

    __syncwarp();

    // ---- output head: y = h_final @ W_out^T + b_out ----
    // T=2048 even -> final h in buffer 0.
    if (llo < OO) {
        const ULL* hf = &hb[wip][0][half][0];
        float ya = b_out[llo];
        float yb = ya;
        #pragma unroll
        for (int j = 0; j < HH; ++j) {
            float ha, hc;
            unpack2(hf[j], ha, hc);
            const float wv = W_out[llo * HH + j];
            ya = fmaf(wv, ha, ya);
            yb = fmaf(wv, hc, yb);
        }
        const size_t r0 = base + 2 * half;
        out[r0 * OO + llo]       = ya;
        out[(r0 + 1) * OO + llo] = yb;
    }
}

extern "C" void kernel_launch(void* const* d_in, const int* in_sizes, int n_in,
                              void* d_out, int out_size)
{
    const float* x     = (const float*)d_in[0];
    const float* W_ih  = (const float*)d_in[1];
    const float* W_hh  = (const float*)d_in[2];
    const float* b_ih  = (const float*)d_in[3];
    const float* b_hh  = (const float*)d_in[4];
    const float* W_out = (const float*)d_in[5];
    const float* b_out = (const float*)d_in[6];
    float* out = (float*)d_out;

    // 4096 rows / (8 warps x 4 rows) = 128 blocks of 256 threads;
    // 1 block/SM, warps w and w+4 share an SMSP with engineered skew.
    rnn_fused_kernel<<<128, 32 * NW>>>(x, W_ih, W_hh, b_ih, b_hh,
                                       W_out, b_out, out);
}